// round 6
// baseline (speedup 1.0000x reference)
#include <cuda_runtime.h>
#include <math.h>

// ---------------------------------------------------------------------------
// Multi-scale morphological closing, [4,8,256,256] -> [4,8,4,256,256]
// closing_k = Vero(Hero(Vdil(Hdil(x)))), parabolic SE, W_k in {4,8,16,32}.
// Two-buffer ping-pong: in_pad -> A -> B -> A -> out keeps the 75MB working
// set L2-resident across the middle passes. A = row-halo layout (stride 256,
// height 256+2W), B = col-halo layout (stride 256+2W, height 256).
// A halos flipped -PADV -> +PADV by extra blocks inside k_heroflip.
// H passes: T=16 outputs/thread for W32/W16, T=8 for W8/W4.
// ---------------------------------------------------------------------------

static constexpr float PADV = 10000.0f;

__host__ __device__ constexpr unsigned WK(int k)  { return 4u << k; }
__host__ __device__ constexpr unsigned HSf(int k) { return 256u + 2u * WK(k); }  // 264,272,288,320
__host__ __device__ constexpr unsigned SZf(int k) { return 256u * HSf(k); }      // per-image floats
__host__ __device__ constexpr size_t  OFFf(int k) {
    return (k == 0) ? 0u
         : (k == 1) ? (size_t)32u * SZf(0)
         : (k == 2) ? (size_t)32u * (SZf(0) + SZf(1))
                    : (size_t)32u * (SZf(0) + SZf(1) + SZf(2));
}
static constexpr size_t TOT = (size_t)32u * (SZf(0) + SZf(1) + SZf(2) + SZf(3)); // 9,371,648

__device__ float g_inpad[320u * 256u * 32u];   // 10.5 MB, col-halo 32 (-PADV)
__device__ float g_A[TOT];                     // 37.5 MB, row-halo layout
__device__ float g_B[TOT];                     // 37.5 MB, col-halo layout (+PADV)

template <int W>
__device__ __forceinline__ constexpr float sew(int x) {
    return (float)(x * x) * (4.0f / (float)(W * W));   // exact in fp32
}

// ---------------- prep: padded input + constant halos (3 tasks) -------------
__global__ void __launch_bounds__(256) k_prep(const float* __restrict__ in)
{
    unsigned f = blockIdx.x * 256u + threadIdx.x;
    unsigned task = blockIdx.y;
    const float4 neg = make_float4(-PADV, -PADV, -PADV, -PADV);
    const float4 pos = make_float4( PADV,  PADV,  PADV,  PADV);

    if (task == 0u) {                        // in_pad: 32 img * 256 rows * 80 f4
        if (f >= 655360u) return;
        unsigned img = f / 20480u, rem = f % 20480u;
        unsigned row = rem / 80u, c4 = rem % 80u;
        float4* d = reinterpret_cast<float4*>(g_inpad) + img * 20480u + row * 80u + c4;
        if (c4 >= 8u && c4 < 72u)
            *d = __ldg(reinterpret_cast<const float4*>(in) + img * 16384u + row * 64u + (c4 - 8u));
        else *d = neg;
        return;
    }
    if (f >= 245760u) return;
    int k; unsigned base;
    if (f < 16384u)       { k = 0; base = 0u; }
    else if (f < 49152u)  { k = 1; base = 16384u; }
    else if (f < 114688u) { k = 2; base = 49152u; }
    else                  { k = 3; base = 114688u; }
    unsigned W = WK(k);
    unsigned local = f - base;
    unsigned HS = HSf(k), SZ = SZf(k);
    size_t OFF = OFFf(k);

    if (task == 1u) {                        // A row halos: -PADV (for dilation)
        unsigned perImg = 2u * W * 64u;
        unsigned img = local / perImg, rem = local % perImg;
        unsigned rowIdx = rem / 64u, c4 = rem % 64u;
        unsigned row = (rowIdx < W) ? rowIdx : (256u + rowIdx);
        float4* d = reinterpret_cast<float4*>(g_A + OFF + (size_t)img * SZ) + row * 64u + c4;
        *d = neg;
    } else {                                 // B col halos: +PADV (for erosion)
        unsigned f4pr = W / 2u;
        unsigned perImg = 256u * f4pr;
        unsigned img = local / perImg, rem = local % perImg;
        unsigned row = rem / f4pr, kk = rem % f4pr;
        unsigned c4 = (kk < W / 4u) ? kk : ((256u + W) / 4u + (kk - W / 4u));
        float4* d = reinterpret_cast<float4*>(g_B + OFF + (size_t)img * SZ) + row * (HS / 4u) + c4;
        *d = pos;
    }
}

// ---------------- horizontal pass: T contiguous outputs/thread --------------
template <int W, int T, bool ISMAX>
__device__ __forceinline__ void hpass(unsigned t, const float* __restrict__ src,
                                      unsigned sIS, unsigned sRS,
                                      float* __restrict__ dst, unsigned dIS, float coef)
{
    constexpr unsigned NG = 256u / T;
    unsigned grp = t % NG, row = t / NG;
    unsigned img = row >> 8, r = row & 255u;
    unsigned p0 = grp * T;
    const float4* s = reinterpret_cast<const float4*>(src + (size_t)img * sIS + (size_t)r * sRS + p0);

    float acc[T];
    constexpr int NLD = (T + 2 * W) / 4;
#pragma unroll
    for (int v = 0; v < NLD; v++) {
        float4 q = __ldg(s + v);
        float qa[4] = {q.x, q.y, q.z, q.w};
#pragma unroll
        for (int c = 0; c < 4; c++) {
            int m = 4 * v + c;
#pragma unroll
            for (int i = 0; i < T; i++) {
                if (m >= i && m <= i + 2 * W) {
                    float wv = ISMAX ? -sew<W>(m - W - i) : sew<W>(m - W - i);
                    float cand = fmaf(coef, wv, qa[c]);     // FFMA-imm
                    if (m == i) acc[i] = cand;
                    else acc[i] = ISMAX ? fmaxf(acc[i], cand) : fminf(acc[i], cand);
                }
            }
        }
    }
    float* d = dst + (size_t)img * dIS + (size_t)r * 256u + p0;
#pragma unroll
    for (int i = 0; i < T; i += 4)
        *reinterpret_cast<float4*>(d + i) = make_float4(acc[i], acc[i+1], acc[i+2], acc[i+3]);
}

// ---------------- vertical pass: 8 rows x 4 cols per thread ------------------
template <int W, bool ISMAX>
__device__ __forceinline__ void vpass(unsigned t, const float* __restrict__ src,
                                      unsigned sIS, float* __restrict__ dst,
                                      unsigned dIS, unsigned dRS, float coef)
{
    unsigned colg = t & 63u, rowg = (t >> 6) & 31u, img = t >> 11;
    unsigned c0 = colg * 4u, r0 = rowg * 8u;
    const float* s = src + (size_t)img * sIS + (size_t)r0 * 256u + c0;

    float4 acc[8];
#pragma unroll
    for (int m = 0; m < 8 + 2 * W; m++) {
        float4 q = __ldg(reinterpret_cast<const float4*>(s + (size_t)m * 256u));
#pragma unroll
        for (int i = 0; i < 8; i++) {
            if (m >= i && m <= i + 2 * W) {
                float wv = ISMAX ? -sew<W>(m - W - i) : sew<W>(m - W - i);
                float4 cd;
                cd.x = fmaf(coef, wv, q.x);
                cd.y = fmaf(coef, wv, q.y);
                cd.z = fmaf(coef, wv, q.z);
                cd.w = fmaf(coef, wv, q.w);
                if (m == i) acc[i] = cd;
                else if (ISMAX) {
                    acc[i].x = fmaxf(acc[i].x, cd.x); acc[i].y = fmaxf(acc[i].y, cd.y);
                    acc[i].z = fmaxf(acc[i].z, cd.z); acc[i].w = fmaxf(acc[i].w, cd.w);
                } else {
                    acc[i].x = fminf(acc[i].x, cd.x); acc[i].y = fminf(acc[i].y, cd.y);
                    acc[i].z = fminf(acc[i].z, cd.z); acc[i].w = fminf(acc[i].w, cd.w);
                }
            }
        }
    }
    float* d = dst + (size_t)img * dIS + (size_t)r0 * dRS + c0;
#pragma unroll
    for (int i = 0; i < 8; i++)
        *reinterpret_cast<float4*>(d + (size_t)i * dRS) = acc[i];
}

// ---------------- pass kernels --------------------------------------------
// H grids: W32 T16 [0,512) | W16 T16 [512,1024) | W8 T8 [1024,2048) | W4 T8 [2048,3072)

__global__ void __launch_bounds__(256, 4) k_hdil(const float* __restrict__ coefp)
{
    float coef = __ldg(coefp);
    unsigned bx = blockIdx.x, tx = threadIdx.x;
    if (bx < 512u)       hpass<32, 16, true>( bx         * 256u + tx, g_inpad + 0,  81920u, 320u, g_A + OFFf(3) + 32u * 256u, SZf(3), coef);
    else if (bx < 1024u) hpass<16, 16, true>((bx - 512u) * 256u + tx, g_inpad + 16, 81920u, 320u, g_A + OFFf(2) + 16u * 256u, SZf(2), coef);
    else if (bx < 2048u) hpass<8,  8,  true>((bx - 1024u) * 256u + tx, g_inpad + 24, 81920u, 320u, g_A + OFFf(1) +  8u * 256u, SZf(1), coef);
    else                 hpass<4,  8,  true>((bx - 2048u) * 256u + tx, g_inpad + 28, 81920u, 320u, g_A + OFFf(0) +  4u * 256u, SZf(0), coef);
}

__global__ void __launch_bounds__(256) k_vdil(const float* __restrict__ coefp)
{
    float coef = __ldg(coefp);
    unsigned bx = blockIdx.x, tx = threadIdx.x;
    if (bx < 256u)       vpass<32, true>( bx         * 256u + tx, g_A + OFFf(3), SZf(3), g_B + OFFf(3) + 32u, SZf(3), HSf(3), coef);
    else if (bx < 512u)  vpass<16, true>((bx - 256u) * 256u + tx, g_A + OFFf(2), SZf(2), g_B + OFFf(2) + 16u, SZf(2), HSf(2), coef);
    else if (bx < 768u)  vpass<8,  true>((bx - 512u) * 256u + tx, g_A + OFFf(1), SZf(1), g_B + OFFf(1) +  8u, SZf(1), HSf(1), coef);
    else                 vpass<4,  true>((bx - 768u) * 256u + tx, g_A + OFFf(0), SZf(0), g_B + OFFf(0) +  4u, SZf(0), HSf(0), coef);
}

// hero + A-halo flip (-PADV -> +PADV) appended as extra blocks [3072, 4032)
__global__ void __launch_bounds__(256, 4) k_heroflip(const float* __restrict__ coefp)
{
    unsigned bx = blockIdx.x, tx = threadIdx.x;
    if (bx >= 3072u) {                       // flip A row halos to +PADV
        unsigned f = (bx - 3072u) * 256u + tx;
        if (f >= 245760u) return;
        int k; unsigned base;
        if (f < 16384u)       { k = 0; base = 0u; }
        else if (f < 49152u)  { k = 1; base = 16384u; }
        else if (f < 114688u) { k = 2; base = 49152u; }
        else                  { k = 3; base = 114688u; }
        unsigned W = WK(k);
        unsigned local = f - base;
        unsigned perImg = 2u * W * 64u;
        unsigned img = local / perImg, rem = local % perImg;
        unsigned rowIdx = rem / 64u, c4 = rem % 64u;
        unsigned row = (rowIdx < W) ? rowIdx : (256u + rowIdx);
        float4* d = reinterpret_cast<float4*>(g_A + OFFf(k) + (size_t)img * SZf(k)) + row * 64u + c4;
        *d = make_float4(PADV, PADV, PADV, PADV);
        return;
    }
    float coef = __ldg(coefp);
    if (bx < 512u)       hpass<32, 16, false>( bx         * 256u + tx, g_B + OFFf(3), SZf(3), HSf(3), g_A + OFFf(3) + 32u * 256u, SZf(3), coef);
    else if (bx < 1024u) hpass<16, 16, false>((bx - 512u) * 256u + tx, g_B + OFFf(2), SZf(2), HSf(2), g_A + OFFf(2) + 16u * 256u, SZf(2), coef);
    else if (bx < 2048u) hpass<8,  8,  false>((bx - 1024u) * 256u + tx, g_B + OFFf(1), SZf(1), HSf(1), g_A + OFFf(1) +  8u * 256u, SZf(1), coef);
    else                 hpass<4,  8,  false>((bx - 2048u) * 256u + tx, g_B + OFFf(0), SZf(0), HSf(0), g_A + OFFf(0) +  4u * 256u, SZf(0), coef);
}

__global__ void __launch_bounds__(256) k_vero(float* __restrict__ out,
                                              const float* __restrict__ coefp)
{
    float coef = __ldg(coefp);
    unsigned bx = blockIdx.x, tx = threadIdx.x;
    // out: [img][scale][256][256], img stride 262144, scale stride 65536
    if (bx < 256u)       vpass<32, false>( bx         * 256u + tx, g_A + OFFf(3), SZf(3), out + 3u * 65536u, 262144u, 256u, coef);
    else if (bx < 512u)  vpass<16, false>((bx - 256u) * 256u + tx, g_A + OFFf(2), SZf(2), out + 2u * 65536u, 262144u, 256u, coef);
    else if (bx < 768u)  vpass<8,  false>((bx - 512u) * 256u + tx, g_A + OFFf(1), SZf(1), out + 1u * 65536u, 262144u, 256u, coef);
    else                 vpass<4,  false>((bx - 768u) * 256u + tx, g_A + OFFf(0), SZf(0), out + 0u * 65536u, 262144u, 256u, coef);
}

extern "C" void kernel_launch(void* const* d_in, const int* in_sizes, int n_in,
                              void* d_out, int out_size)
{
    const float* in   = (const float*)d_in[0];
    const float* coef = (const float*)d_in[1];
    float* out        = (float*)d_out;

    dim3 gprep(2560, 3);
    k_prep<<<gprep, 256>>>(in);            // padded input + constant halos
    k_hdil<<<3072, 256>>>(coef);           // H dilate: in_pad -> A
    k_vdil<<<1024, 256>>>(coef);           // V dilate: A -> B
    k_heroflip<<<4032, 256>>>(coef);       // H erode : B -> A  (+ flip A halos)
    k_vero<<<1024, 256>>>(out, coef);      // V erode : A -> out
}

// round 7
// speedup vs baseline: 1.0394x; 1.0394x over previous
#include <cuda_runtime.h>
#include <math.h>

// ---------------------------------------------------------------------------
// Multi-scale morphological closing, [4,8,256,256] -> [4,8,4,256,256]
// closing_k = Vero(Hero(Vdil(Hdil(x)))), parabolic SE, W_k in {4,8,16,32}.
// Ping-pong: in_pad -> A -> B -> A -> out (75MB hot set). A = row-halo layout
// (stride 256, height 256+2W), B = col-halo layout (stride 256+2W, height 256).
// A halos flipped -PADV -> +PADV by extra blocks in k_heroflip.
// H passes: T=8 outputs/thread (proven best). V passes: 8 rows x 2 cols,
// 16 acc regs, __launch_bounds__(256,8) for full occupancy.
// ---------------------------------------------------------------------------

static constexpr float PADV = 10000.0f;

__host__ __device__ constexpr unsigned WK(int k)  { return 4u << k; }
__host__ __device__ constexpr unsigned HSf(int k) { return 256u + 2u * WK(k); }  // 264,272,288,320
__host__ __device__ constexpr unsigned SZf(int k) { return 256u * HSf(k); }      // per-image floats
__host__ __device__ constexpr size_t  OFFf(int k) {
    return (k == 0) ? 0u
         : (k == 1) ? (size_t)32u * SZf(0)
         : (k == 2) ? (size_t)32u * (SZf(0) + SZf(1))
                    : (size_t)32u * (SZf(0) + SZf(1) + SZf(2));
}
static constexpr size_t TOT = (size_t)32u * (SZf(0) + SZf(1) + SZf(2) + SZf(3)); // 9,371,648

__device__ float g_inpad[320u * 256u * 32u];   // 10.5 MB, col-halo 32 (-PADV)
__device__ float g_A[TOT];                     // 37.5 MB, row-halo layout
__device__ float g_B[TOT];                     // 37.5 MB, col-halo layout (+PADV)

template <int W>
__device__ __forceinline__ constexpr float sew(int x) {
    return (float)(x * x) * (4.0f / (float)(W * W));   // exact in fp32
}

// ---------------- prep: padded input + constant halos (3 tasks) -------------
__global__ void __launch_bounds__(256) k_prep(const float* __restrict__ in)
{
    unsigned f = blockIdx.x * 256u + threadIdx.x;
    unsigned task = blockIdx.y;
    const float4 neg = make_float4(-PADV, -PADV, -PADV, -PADV);
    const float4 pos = make_float4( PADV,  PADV,  PADV,  PADV);

    if (task == 0u) {                        // in_pad: 32 img * 256 rows * 80 f4
        if (f >= 655360u) return;
        unsigned img = f / 20480u, rem = f % 20480u;
        unsigned row = rem / 80u, c4 = rem % 80u;
        float4* d = reinterpret_cast<float4*>(g_inpad) + img * 20480u + row * 80u + c4;
        if (c4 >= 8u && c4 < 72u)
            *d = __ldg(reinterpret_cast<const float4*>(in) + img * 16384u + row * 64u + (c4 - 8u));
        else *d = neg;
        return;
    }
    if (f >= 245760u) return;
    int k; unsigned base;
    if (f < 16384u)       { k = 0; base = 0u; }
    else if (f < 49152u)  { k = 1; base = 16384u; }
    else if (f < 114688u) { k = 2; base = 49152u; }
    else                  { k = 3; base = 114688u; }
    unsigned W = WK(k);
    unsigned local = f - base;
    unsigned HS = HSf(k), SZ = SZf(k);
    size_t OFF = OFFf(k);

    if (task == 1u) {                        // A row halos: -PADV (for dilation)
        unsigned perImg = 2u * W * 64u;
        unsigned img = local / perImg, rem = local % perImg;
        unsigned rowIdx = rem / 64u, c4 = rem % 64u;
        unsigned row = (rowIdx < W) ? rowIdx : (256u + rowIdx);
        float4* d = reinterpret_cast<float4*>(g_A + OFF + (size_t)img * SZ) + row * 64u + c4;
        *d = neg;
    } else {                                 // B col halos: +PADV (for erosion)
        unsigned f4pr = W / 2u;
        unsigned perImg = 256u * f4pr;
        unsigned img = local / perImg, rem = local % perImg;
        unsigned row = rem / f4pr, kk = rem % f4pr;
        unsigned c4 = (kk < W / 4u) ? kk : ((256u + W) / 4u + (kk - W / 4u));
        float4* d = reinterpret_cast<float4*>(g_B + OFF + (size_t)img * SZ) + row * (HS / 4u) + c4;
        *d = pos;
    }
}

// ---------------- horizontal pass: 8 contiguous outputs/thread --------------
template <int W, bool ISMAX>
__device__ __forceinline__ void hpass(unsigned t, const float* __restrict__ src,
                                      unsigned sIS, unsigned sRS,
                                      float* __restrict__ dst, unsigned dIS, float coef)
{
    unsigned grp = t & 31u, row = t >> 5;
    unsigned img = row >> 8, r = row & 255u;
    unsigned p0 = grp * 8u;
    const float4* s = reinterpret_cast<const float4*>(src + (size_t)img * sIS + (size_t)r * sRS + p0);

    float acc[8];
    constexpr int NLD = (8 + 2 * W) / 4;
#pragma unroll
    for (int v = 0; v < NLD; v++) {
        float4 q = __ldg(s + v);
        float qa[4] = {q.x, q.y, q.z, q.w};
#pragma unroll
        for (int c = 0; c < 4; c++) {
            int m = 4 * v + c;
#pragma unroll
            for (int i = 0; i < 8; i++) {
                if (m >= i && m <= i + 2 * W) {
                    float wv = ISMAX ? -sew<W>(m - W - i) : sew<W>(m - W - i);
                    float cand = fmaf(coef, wv, qa[c]);     // FFMA-imm
                    if (m == i) acc[i] = cand;
                    else acc[i] = ISMAX ? fmaxf(acc[i], cand) : fminf(acc[i], cand);
                }
            }
        }
    }
    float* d = dst + (size_t)img * dIS + (size_t)r * 256u + p0;
    *reinterpret_cast<float4*>(d)     = make_float4(acc[0], acc[1], acc[2], acc[3]);
    *reinterpret_cast<float4*>(d + 4) = make_float4(acc[4], acc[5], acc[6], acc[7]);
}

// ---------------- vertical pass: 8 rows x 2 cols per thread ------------------
// src stride 256; window starts at buffer row r0. dst pre-offset to interior.
template <int W, bool ISMAX>
__device__ __forceinline__ void vpass(unsigned t, const float* __restrict__ src,
                                      unsigned sIS, float* __restrict__ dst,
                                      unsigned dIS, unsigned dRS, float coef)
{
    unsigned colg = t & 127u, rowg = (t >> 7) & 31u, img = t >> 12;
    unsigned c0 = colg * 2u, r0 = rowg * 8u;
    const float* s = src + (size_t)img * sIS + (size_t)r0 * 256u + c0;

    float2 acc[8];
#pragma unroll
    for (int m = 0; m < 8 + 2 * W; m++) {
        float2 q = __ldg(reinterpret_cast<const float2*>(s + (size_t)m * 256u));
#pragma unroll
        for (int i = 0; i < 8; i++) {
            if (m >= i && m <= i + 2 * W) {
                float wv = ISMAX ? -sew<W>(m - W - i) : sew<W>(m - W - i);
                float2 cd;
                cd.x = fmaf(coef, wv, q.x);
                cd.y = fmaf(coef, wv, q.y);
                if (m == i) acc[i] = cd;
                else if (ISMAX) {
                    acc[i].x = fmaxf(acc[i].x, cd.x); acc[i].y = fmaxf(acc[i].y, cd.y);
                } else {
                    acc[i].x = fminf(acc[i].x, cd.x); acc[i].y = fminf(acc[i].y, cd.y);
                }
            }
        }
    }
    float* d = dst + (size_t)img * dIS + (size_t)r0 * dRS + c0;
#pragma unroll
    for (int i = 0; i < 8; i++)
        *reinterpret_cast<float2*>(d + (size_t)i * dRS) = acc[i];
}

// ---------------- pass kernels --------------------------------------------
// H grids: 1024 blocks/scale, heavy (W32) first.
// V grids: 512 blocks/scale, heavy first.

__global__ void __launch_bounds__(256) k_hdil(const float* __restrict__ coefp)
{
    float coef = __ldg(coefp);
    unsigned bx = blockIdx.x, tx = threadIdx.x;
    if (bx < 1024u)      hpass<32, true>( bx          * 256u + tx, g_inpad + 0,  81920u, 320u, g_A + OFFf(3) + 32u * 256u, SZf(3), coef);
    else if (bx < 2048u) hpass<16, true>((bx - 1024u) * 256u + tx, g_inpad + 16, 81920u, 320u, g_A + OFFf(2) + 16u * 256u, SZf(2), coef);
    else if (bx < 3072u) hpass<8,  true>((bx - 2048u) * 256u + tx, g_inpad + 24, 81920u, 320u, g_A + OFFf(1) +  8u * 256u, SZf(1), coef);
    else                 hpass<4,  true>((bx - 3072u) * 256u + tx, g_inpad + 28, 81920u, 320u, g_A + OFFf(0) +  4u * 256u, SZf(0), coef);
}

__global__ void __launch_bounds__(256, 8) k_vdil(const float* __restrict__ coefp)
{
    float coef = __ldg(coefp);
    unsigned bx = blockIdx.x, tx = threadIdx.x;
    if (bx < 512u)       vpass<32, true>( bx          * 256u + tx, g_A + OFFf(3), SZf(3), g_B + OFFf(3) + 32u, SZf(3), HSf(3), coef);
    else if (bx < 1024u) vpass<16, true>((bx - 512u)  * 256u + tx, g_A + OFFf(2), SZf(2), g_B + OFFf(2) + 16u, SZf(2), HSf(2), coef);
    else if (bx < 1536u) vpass<8,  true>((bx - 1024u) * 256u + tx, g_A + OFFf(1), SZf(1), g_B + OFFf(1) +  8u, SZf(1), HSf(1), coef);
    else                 vpass<4,  true>((bx - 1536u) * 256u + tx, g_A + OFFf(0), SZf(0), g_B + OFFf(0) +  4u, SZf(0), HSf(0), coef);
}

// hero + A-halo flip (-PADV -> +PADV) appended as blocks [4096, 5056)
__global__ void __launch_bounds__(256) k_heroflip(const float* __restrict__ coefp)
{
    unsigned bx = blockIdx.x, tx = threadIdx.x;
    if (bx >= 4096u) {                       // flip A row halos to +PADV
        unsigned f = (bx - 4096u) * 256u + tx;
        if (f >= 245760u) return;
        int k; unsigned base;
        if (f < 16384u)       { k = 0; base = 0u; }
        else if (f < 49152u)  { k = 1; base = 16384u; }
        else if (f < 114688u) { k = 2; base = 49152u; }
        else                  { k = 3; base = 114688u; }
        unsigned W = WK(k);
        unsigned local = f - base;
        unsigned perImg = 2u * W * 64u;
        unsigned img = local / perImg, rem = local % perImg;
        unsigned rowIdx = rem / 64u, c4 = rem % 64u;
        unsigned row = (rowIdx < W) ? rowIdx : (256u + rowIdx);
        float4* d = reinterpret_cast<float4*>(g_A + OFFf(k) + (size_t)img * SZf(k)) + row * 64u + c4;
        *d = make_float4(PADV, PADV, PADV, PADV);
        return;
    }
    float coef = __ldg(coefp);
    if (bx < 1024u)      hpass<32, false>( bx          * 256u + tx, g_B + OFFf(3), SZf(3), HSf(3), g_A + OFFf(3) + 32u * 256u, SZf(3), coef);
    else if (bx < 2048u) hpass<16, false>((bx - 1024u) * 256u + tx, g_B + OFFf(2), SZf(2), HSf(2), g_A + OFFf(2) + 16u * 256u, SZf(2), coef);
    else if (bx < 3072u) hpass<8,  false>((bx - 2048u) * 256u + tx, g_B + OFFf(1), SZf(1), HSf(1), g_A + OFFf(1) +  8u * 256u, SZf(1), coef);
    else                 hpass<4,  false>((bx - 3072u) * 256u + tx, g_B + OFFf(0), SZf(0), HSf(0), g_A + OFFf(0) +  4u * 256u, SZf(0), coef);
}

__global__ void __launch_bounds__(256, 8) k_vero(float* __restrict__ out,
                                                 const float* __restrict__ coefp)
{
    float coef = __ldg(coefp);
    unsigned bx = blockIdx.x, tx = threadIdx.x;
    // out: [img][scale][256][256], img stride 262144, scale stride 65536
    if (bx < 512u)       vpass<32, false>( bx          * 256u + tx, g_A + OFFf(3), SZf(3), out + 3u * 65536u, 262144u, 256u, coef);
    else if (bx < 1024u) vpass<16, false>((bx - 512u)  * 256u + tx, g_A + OFFf(2), SZf(2), out + 2u * 65536u, 262144u, 256u, coef);
    else if (bx < 1536u) vpass<8,  false>((bx - 1024u) * 256u + tx, g_A + OFFf(1), SZf(1), out + 1u * 65536u, 262144u, 256u, coef);
    else                 vpass<4,  false>((bx - 1536u) * 256u + tx, g_A + OFFf(0), SZf(0), out + 0u * 65536u, 262144u, 256u, coef);
}

extern "C" void kernel_launch(void* const* d_in, const int* in_sizes, int n_in,
                              void* d_out, int out_size)
{
    const float* in   = (const float*)d_in[0];
    const float* coef = (const float*)d_in[1];
    float* out        = (float*)d_out;

    dim3 gprep(2560, 3);
    k_prep<<<gprep, 256>>>(in);            // padded input + constant halos
    k_hdil<<<4096, 256>>>(coef);           // H dilate: in_pad -> A
    k_vdil<<<2048, 256>>>(coef);           // V dilate: A -> B
    k_heroflip<<<5056, 256>>>(coef);       // H erode : B -> A  (+ flip A halos)
    k_vero<<<2048, 256>>>(out, coef);      // V erode : A -> out
}